// round 4
// baseline (speedup 1.0000x reference)
#include <cuda_runtime.h>
#include <cstdint>

#define TSTEPS 512
#define H 20
#define BPB 32          // batches per block
#define NTHREADS 160    // 5 warps: L0 | L1a | L1b | L2a | L2b
#define NBLOCKS 256

typedef unsigned long long u64;

// ---------------- constant parameter bank (packed by pack_params) ----------
// floats: [0:400) w_hh0 | [400:800) w_ih1 | [800:1200) w_hh1 |
//         [1200:1600) w_ih2 | [1600:2000) w_hh2 | [2000:2020) w_ih0 |
//         [2020:2040) b0=b_ih0+b_hh0 | [2040:2060) b1 | [2060:2080) b2 |
//         [2080:2100) fc_w | [2100] fc_b
#define OFF_WHH0 0
#define OFF_WIH1 400
#define OFF_WHH1 800
#define OFF_WIH2 1200
#define OFF_WHH2 1600
#define OFF_WIH0 2000
#define OFF_B0   2020
#define OFF_B1   2040
#define OFF_B2   2060
#define OFF_FCW  2080
#define OFF_FCB  2100

__constant__ float cP[2112];
__device__   float g_stage[2112];

__global__ void pack_params(
    const float* __restrict__ w_ih0, const float* __restrict__ w_hh0,
    const float* __restrict__ b_ih0, const float* __restrict__ b_hh0,
    const float* __restrict__ w_ih1, const float* __restrict__ w_hh1,
    const float* __restrict__ b_ih1, const float* __restrict__ b_hh1,
    const float* __restrict__ w_ih2, const float* __restrict__ w_hh2,
    const float* __restrict__ b_ih2, const float* __restrict__ b_hh2,
    const float* __restrict__ fc_w,  const float* __restrict__ fc_b)
{
    int i = threadIdx.x;
    if (i < 400) {
        g_stage[OFF_WHH0 + i] = w_hh0[i];
        g_stage[OFF_WIH1 + i] = w_ih1[i];
        g_stage[OFF_WHH1 + i] = w_hh1[i];
        g_stage[OFF_WIH2 + i] = w_ih2[i];
        g_stage[OFF_WHH2 + i] = w_hh2[i];
    }
    if (i < 20) {
        g_stage[OFF_WIH0 + i] = w_ih0[i];
        g_stage[OFF_B0 + i]   = b_ih0[i] + b_hh0[i];
        g_stage[OFF_B1 + i]   = b_ih1[i] + b_hh1[i];
        g_stage[OFF_B2 + i]   = b_ih2[i] + b_hh2[i];
        g_stage[OFF_FCW + i]  = fc_w[i];
    }
    if (i == 0) g_stage[OFF_FCB] = fc_b[0];
}

// ---------------- math helpers --------------------------------------------
__device__ __forceinline__ void ffma2(u64& acc, u64 a, u64 b) {
    asm("fma.rn.f32x2 %0, %1, %2, %0;" : "+l"(acc) : "l"(a), "l"(b));
}
__device__ __forceinline__ u64 pack2(float lo, float hi) {
    u64 r; asm("mov.b64 %0, {%1, %2};" : "=l"(r) : "f"(lo), "f"(hi)); return r;
}
__device__ __forceinline__ float2 unpack2(u64 v) {
    float2 r; asm("mov.b64 {%0, %1}, %2;" : "=f"(r.x), "=f"(r.y) : "l"(v)); return r;
}
// tanh(x) = 1 - 2/(e^{2x}+1); ex2.approx+rcp.approx, abs err ~1e-7.
// Large |x| handled by ex2 -> 0 / inf (rcp(inf)=0) -- no clamp needed.
__device__ __forceinline__ float tanh_fast(float x) {
    float e;
    asm("ex2.approx.f32 %0, %1;" : "=f"(e) : "f"(x * 2.8853900817779268f));
    float rr;
    asm("rcp.approx.f32 %0, %1;" : "=f"(rr) : "f"(e + 1.0f));
    return fmaf(-2.0f, rr, 1.0f);
}

// ---------------- main pipelined kernel ------------------------------------
// Block: 32 batches. Warp roles:
//   warp0: layer 0 (all 20 rows), processes t = s
//   warp1: layer 1 rows 0-9,  t = s-1     warp2: layer 1 rows 10-19
//   warp3: layer 2 rows 0-9,  t = s-2     warp4: layer 2 rows 10-19
// Hidden states ping-pong through hrow[slot][layer][b][20]; writers use
// slot s&1, readers use (s&1)^1; one __syncthreads per step.
__global__ __launch_bounds__(NTHREADS)
void rnn3_pipe(const float* __restrict__ x, float* __restrict__ out)
{
    __shared__ __align__(16) float hrow[2][3][BPB][H];   // 15360 B

    const int tid  = threadIdx.x;
    const int warp = tid >> 5;
    const int lane = tid & 31;
    const int bglob = blockIdx.x * BPB + lane;

    for (int i = tid; i < 2 * 3 * BPB * H; i += NTHREADS)
        (&hrow[0][0][0][0])[i] = 0.0f;
    __syncthreads();

    if (warp == 0) {
        // ---------------- layer 0 ----------------
        float wx[H], bs[H];
#pragma unroll
        for (int j = 0; j < H; j++) { wx[j] = cP[OFF_WIH0 + j]; bs[j] = cP[OFF_B0 + j]; }
        const float* xrow = x + (size_t)bglob * TSTEPS;
        float4 xq = make_float4(0.f, 0.f, 0.f, 0.f);

#pragma unroll 1
        for (int s = 0; s < TSTEPS + 2; s++) {
            if (s < TSTEPS) {
                const int rp = (s & 1) ^ 1, wp = s & 1;
                if ((s & 3) == 0) xq = __ldg((const float4*)(xrow + s));
                const int ph = s & 3;
                const float xv = (ph == 0) ? xq.x : (ph == 1) ? xq.y : (ph == 2) ? xq.z : xq.w;

                u64 hp[10];
                const ulonglong2* hr = (const ulonglong2*)&hrow[rp][0][lane][0];
#pragma unroll
                for (int q = 0; q < 5; q++) { ulonglong2 v = hr[q]; hp[2*q] = v.x; hp[2*q+1] = v.y; }

                float hn[H];
#pragma unroll
                for (int j = 0; j < H; j++) {
                    const ulonglong2* wr = (const ulonglong2*)&cP[OFF_WHH0 + j * H];
                    u64 acc = pack2(fmaf(xv, wx[j], bs[j]), 0.0f);
#pragma unroll
                    for (int q = 0; q < 5; q++) {
                        ulonglong2 w2 = wr[q];
                        ffma2(acc, hp[2*q],     w2.x);
                        ffma2(acc, hp[2*q + 1], w2.y);
                    }
                    float2 p = unpack2(acc);
                    hn[j] = tanh_fast(p.x + p.y);
                }
                ulonglong2* hw = (ulonglong2*)&hrow[wp][0][lane][0];
#pragma unroll
                for (int q = 0; q < 5; q++) {
                    ulonglong2 v;
                    v.x = pack2(hn[4*q],     hn[4*q + 1]);
                    v.y = pack2(hn[4*q + 2], hn[4*q + 3]);
                    hw[q] = v;
                }
            }
            __syncthreads();
        }

        // ---------------- FC epilogue (h2 final lives in slot 1) ----------
        {
            const float* h2 = &hrow[1][2][lane][0];
            float sacc = cP[OFF_FCB];
#pragma unroll
            for (int j = 0; j < H; j++) sacc = fmaf(h2[j], cP[OFF_FCW + j], sacc);
            out[bglob] = sacc;
        }
    } else {
        // ---------------- layers 1 / 2, split by row-half ------------------
        const int L    = (warp <= 2) ? 1 : 2;
        const int j0   = (warp & 1) ? 0 : 10;    // warps 1,3 -> rows 0-9; 2,4 -> 10-19
        const int offI = (L == 1) ? OFF_WIH1 : OFF_WIH2;
        const int offH = (L == 1) ? OFF_WHH1 : OFF_WHH2;
        const int offB = (L == 1) ? OFF_B1   : OFF_B2;

        float bs[10];
#pragma unroll
        for (int j = 0; j < 10; j++) bs[j] = cP[offB + j0 + j];

#pragma unroll 1
        for (int s = 0; s < TSTEPS + 2; s++) {
            const int t = s - L;
            if (t >= 0 && t < TSTEPS) {
                const int rp = (s & 1) ^ 1, wp = s & 1;
                u64 ha[10], hb[10];
                const ulonglong2* hA = (const ulonglong2*)&hrow[rp][L - 1][lane][0]; // input seq
                const ulonglong2* hB = (const ulonglong2*)&hrow[rp][L][lane][0];     // own recur
#pragma unroll
                for (int q = 0; q < 5; q++) {
                    ulonglong2 va = hA[q]; ha[2*q] = va.x; ha[2*q+1] = va.y;
                    ulonglong2 vb = hB[q]; hb[2*q] = vb.x; hb[2*q+1] = vb.y;
                }
                float hn[10];
#pragma unroll
                for (int j = 0; j < 10; j++) {
                    const ulonglong2* wi = (const ulonglong2*)&cP[offI + (j0 + j) * H];
                    const ulonglong2* wh = (const ulonglong2*)&cP[offH + (j0 + j) * H];
                    u64 acc = pack2(bs[j], 0.0f);
#pragma unroll
                    for (int q = 0; q < 5; q++) {
                        ulonglong2 wiv = wi[q], whv = wh[q];
                        ffma2(acc, ha[2*q],     wiv.x);
                        ffma2(acc, ha[2*q + 1], wiv.y);
                        ffma2(acc, hb[2*q],     whv.x);
                        ffma2(acc, hb[2*q + 1], whv.y);
                    }
                    float2 p = unpack2(acc);
                    hn[j] = tanh_fast(p.x + p.y);
                }
                u64* hw = (u64*)&hrow[wp][L][lane][j0];
#pragma unroll
                for (int q = 0; q < 5; q++)
                    hw[q] = pack2(hn[2*q], hn[2*q + 1]);
            }
            __syncthreads();
        }
    }
}

extern "C" void kernel_launch(void* const* d_in, const int* in_sizes, int n_in,
                              void* d_out, int out_size) {
    (void)in_sizes; (void)n_in; (void)out_size;
    pack_params<<<1, 512>>>(
        (const float*)d_in[1],  (const float*)d_in[2],
        (const float*)d_in[3],  (const float*)d_in[4],
        (const float*)d_in[5],  (const float*)d_in[6],
        (const float*)d_in[7],  (const float*)d_in[8],
        (const float*)d_in[9],  (const float*)d_in[10],
        (const float*)d_in[11], (const float*)d_in[12],
        (const float*)d_in[13], (const float*)d_in[14]);

    void* stage_ptr = nullptr;
    cudaGetSymbolAddress(&stage_ptr, g_stage);
    cudaMemcpyToSymbolAsync(cP, stage_ptr, 2112 * sizeof(float), 0,
                            cudaMemcpyDeviceToDevice, 0);

    rnn3_pipe<<<NBLOCKS, NTHREADS>>>((const float*)d_in[0], (float*)d_out);
}

// round 5
// speedup vs baseline: 2.4255x; 2.4255x over previous
#include <cuda_runtime.h>
#include <cstdint>

#define TSTEPS 512
#define H 20
#define BPB 32          // batches/block: 2 warps x 8 groups x 2 batches
#define NTHREADS 64
#define NBLOCKS 256
#define SUBSTRIDE 2008  // floats per sub-copy (2000 + 8 pad -> distinct 16B phases)

typedef unsigned long long u64;

__device__ __forceinline__ void ffma2(u64& acc, u64 a, u64 b) {
    asm("fma.rn.f32x2 %0, %1, %2, %0;" : "+l"(acc) : "l"(a), "l"(b));
}
__device__ __forceinline__ u64 pack2(float lo, float hi) {
    u64 r; asm("mov.b64 %0, {%1, %2};" : "=l"(r) : "f"(lo), "f"(hi)); return r;
}
__device__ __forceinline__ float2 unpack2(u64 v) {
    float2 r; asm("mov.b64 {%0, %1}, %2;" : "=f"(r.x), "=f"(r.y) : "l"(v)); return r;
}
// tanh via ex2.approx + rcp.approx, abs err ~2e-7
__device__ __forceinline__ float tanh_fast(float x) {
    float ax = fminf(fabsf(x), 15.0f);
    float e;
    asm("ex2.approx.f32 %0, %1;" : "=f"(e) : "f"(ax * 2.8853900817779268f));
    float rr;
    asm("rcp.approx.f32 %0, %1;" : "=f"(rr) : "f"(e + 1.0f));
    return copysignf((e - 1.0f) * rr, x);
}

// Butterfly gather within a 4-lane group: input = own 5 h values, output =
// all 20 h values k-pair-packed as u64[10], in per-lane block order
// [sub, sub^1, sub^2, sub^3] (weights in smem are pre-permuted to match).
__device__ __forceinline__ void gather20(const float v[5], u64 hp[10]) {
    float a[10];
#pragma unroll
    for (int i = 0; i < 5; i++) {
        a[i]     = v[i];
        a[5 + i] = __shfl_xor_sync(0xffffffffu, v[i], 1);
    }
#pragma unroll
    for (int q = 0; q < 5; q++) hp[q] = pack2(a[2 * q], a[2 * q + 1]);
    float b[10];
#pragma unroll
    for (int i = 0; i < 10; i++) b[i] = __shfl_xor_sync(0xffffffffu, a[i], 2);
#pragma unroll
    for (int q = 0; q < 5; q++) hp[5 + q] = pack2(b[2 * q], b[2 * q + 1]);
}

__global__ __launch_bounds__(NTHREADS)
void rnn3_kernel(
    const float* __restrict__ x,
    const float* __restrict__ w_ih0, const float* __restrict__ w_hh0,
    const float* __restrict__ b_ih0, const float* __restrict__ b_hh0,
    const float* __restrict__ w_ih1, const float* __restrict__ w_hh1,
    const float* __restrict__ b_ih1, const float* __restrict__ b_hh1,
    const float* __restrict__ w_ih2, const float* __restrict__ w_hh2,
    const float* __restrict__ b_ih2, const float* __restrict__ b_hh2,
    const float* __restrict__ fc_w, const float* __restrict__ fc_b,
    float* __restrict__ out)
{
    // per-sub permuted weight copies: wp[sub][m][j][k],
    // column k maps to original column 5*(sub ^ (k/5)) + k%5.
    // matrices m: 0=w_hh0 1=w_ih1 2=w_hh1 3=w_ih2 4=w_hh2
    __shared__ __align__(16) float wp[4 * SUBSTRIDE];   // 32128 B

    const int tid = threadIdx.x;

    for (int idx = tid; idx < 4 * 2000; idx += NTHREADS) {
        int s   = idx / 2000;
        int rem = idx % 2000;
        int m   = rem / 400;
        int r   = rem % 400;
        int j   = r / H;
        int k   = r % H;
        int oc  = 5 * (s ^ (k / 5)) + (k % 5);
        const float* src = (m == 0) ? w_hh0 : (m == 1) ? w_ih1 :
                           (m == 2) ? w_hh1 : (m == 3) ? w_ih2 : w_hh2;
        wp[s * SUBSTRIDE + (m * H + j) * H + k] = src[j * H + oc];
    }
    __syncthreads();

    const int lane = tid & 31;
    const int warp = tid >> 5;
    const int gi   = lane >> 2;
    const int sub  = lane & 3;
    const int bib0 = warp * 8 + gi;
    const int bib1 = 16 + warp * 8 + gi;
    const int b0   = blockIdx.x * BPB + bib0;
    const int b1   = blockIdx.x * BPB + bib1;
    const int j0   = sub * 5;

    // sub's permuted weight base; matrix m row jj quads at wmS + m*400 + jj*20
    const float* wsub = wp + sub * SUBSTRIDE + j0 * H;

    float bias0[5], bias1[5], bias2[5], wih0r[5];
#pragma unroll
    for (int jj = 0; jj < 5; jj++) {
        int j = j0 + jj;
        bias0[jj] = b_ih0[j] + b_hh0[j];
        bias1[jj] = b_ih1[j] + b_hh1[j];
        bias2[jj] = b_ih2[j] + b_hh2[j];
        wih0r[jj] = w_ih0[j];
    }

    const float* xrow0 = x + (size_t)b0 * TSTEPS;
    const float* xrow1 = x + (size_t)b1 * TSTEPS;

    // persistent state (registers only)
    u64 hp0[2][10], hp1[2][10];     // gathered h0, h1 (k-pair packed)
    float h2own[2][5];              // own 5 rows of h2
#pragma unroll
    for (int q = 0; q < 10; q++) { hp0[0][q] = 0; hp0[1][q] = 0; hp1[0][q] = 0; hp1[1][q] = 0; }
#pragma unroll
    for (int jj = 0; jj < 5; jj++) { h2own[0][jj] = 0.f; h2own[1][jj] = 0.f; }

    float4 xq0 = make_float4(0.f,0.f,0.f,0.f), xq1 = xq0;

#pragma unroll 1
    for (int t = 0; t < TSTEPS; t++) {
        if ((t & 3) == 0) {
            xq0 = __ldg((const float4*)(xrow0 + t));
            xq1 = __ldg((const float4*)(xrow1 + t));
        }
        const int ph = t & 3;
        const float xv0 = (ph == 0) ? xq0.x : (ph == 1) ? xq0.y : (ph == 2) ? xq0.z : xq0.w;
        const float xv1 = (ph == 0) ? xq1.x : (ph == 1) ? xq1.y : (ph == 2) ? xq1.z : xq1.w;

        // ===== Layer 0: h0' = tanh(x*wih0 + bias0 + whh0 @ h0) =====
        float h0n0[5], h0n1[5];
        {
            u64 a0[5], a1[5];
#pragma unroll
            for (int jj = 0; jj < 5; jj++) {
                a0[jj] = pack2(fmaf(xv0, wih0r[jj], bias0[jj]), 0.f);
                a1[jj] = pack2(fmaf(xv1, wih0r[jj], bias0[jj]), 0.f);
            }
            const float* wm = wsub;  // m = 0
#pragma unroll
            for (int q = 0; q < 5; q++) {
#pragma unroll
                for (int jj = 0; jj < 5; jj++) {
                    ulonglong2 wv = ((const ulonglong2*)(wm + jj * H))[q];
                    ffma2(a0[jj], hp0[0][2*q],   wv.x);
                    ffma2(a0[jj], hp0[0][2*q+1], wv.y);
                    ffma2(a1[jj], hp0[1][2*q],   wv.x);
                    ffma2(a1[jj], hp0[1][2*q+1], wv.y);
                }
            }
#pragma unroll
            for (int jj = 0; jj < 5; jj++) {
                float2 p0 = unpack2(a0[jj]); h0n0[jj] = tanh_fast(p0.x + p0.y);
                float2 p1 = unpack2(a1[jj]); h0n1[jj] = tanh_fast(p1.x + p1.y);
            }
        }
        gather20(h0n0, hp0[0]);
        gather20(h0n1, hp0[1]);

        // ===== Layer 1: h1' = tanh(wih1 @ h0' + bias1 + whh1 @ h1) =====
        float h1n0[5], h1n1[5];
        {
            u64 a0[5], a1[5];
#pragma unroll
            for (int jj = 0; jj < 5; jj++) { a0[jj] = pack2(bias1[jj], 0.f); a1[jj] = pack2(bias1[jj], 0.f); }
            const float* wi = wsub + 400;   // m = 1
            const float* wh = wsub + 800;   // m = 2
#pragma unroll
            for (int q = 0; q < 5; q++) {
#pragma unroll
                for (int jj = 0; jj < 5; jj++) {
                    ulonglong2 wiv = ((const ulonglong2*)(wi + jj * H))[q];
                    ulonglong2 whv = ((const ulonglong2*)(wh + jj * H))[q];
                    ffma2(a0[jj], hp0[0][2*q],   wiv.x);
                    ffma2(a0[jj], hp0[0][2*q+1], wiv.y);
                    ffma2(a0[jj], hp1[0][2*q],   whv.x);
                    ffma2(a0[jj], hp1[0][2*q+1], whv.y);
                    ffma2(a1[jj], hp0[1][2*q],   wiv.x);
                    ffma2(a1[jj], hp0[1][2*q+1], wiv.y);
                    ffma2(a1[jj], hp1[1][2*q],   whv.x);
                    ffma2(a1[jj], hp1[1][2*q+1], whv.y);
                }
            }
#pragma unroll
            for (int jj = 0; jj < 5; jj++) {
                float2 p0 = unpack2(a0[jj]); h1n0[jj] = tanh_fast(p0.x + p0.y);
                float2 p1 = unpack2(a1[jj]); h1n1[jj] = tanh_fast(p1.x + p1.y);
            }
        }
        gather20(h1n0, hp1[0]);
        gather20(h1n1, hp1[1]);

        // ===== Layer 2: h2' = tanh(wih2 @ h1' + bias2 + whh2 @ h2) =====
        {
            u64 hp2a[10], hp2b[10];
            gather20(h2own[0], hp2a);
            gather20(h2own[1], hp2b);
            u64 a0[5], a1[5];
#pragma unroll
            for (int jj = 0; jj < 5; jj++) { a0[jj] = pack2(bias2[jj], 0.f); a1[jj] = pack2(bias2[jj], 0.f); }
            const float* wi = wsub + 1200;  // m = 3
            const float* wh = wsub + 1600;  // m = 4
#pragma unroll
            for (int q = 0; q < 5; q++) {
#pragma unroll
                for (int jj = 0; jj < 5; jj++) {
                    ulonglong2 wiv = ((const ulonglong2*)(wi + jj * H))[q];
                    ulonglong2 whv = ((const ulonglong2*)(wh + jj * H))[q];
                    ffma2(a0[jj], hp1[0][2*q],   wiv.x);
                    ffma2(a0[jj], hp1[0][2*q+1], wiv.y);
                    ffma2(a0[jj], hp2a[2*q],     whv.x);
                    ffma2(a0[jj], hp2a[2*q+1],   whv.y);
                    ffma2(a1[jj], hp1[1][2*q],   wiv.x);
                    ffma2(a1[jj], hp1[1][2*q+1], wiv.y);
                    ffma2(a1[jj], hp2b[2*q],     whv.x);
                    ffma2(a1[jj], hp2b[2*q+1],   whv.y);
                }
            }
#pragma unroll
            for (int jj = 0; jj < 5; jj++) {
                float2 p0 = unpack2(a0[jj]); h2own[0][jj] = tanh_fast(p0.x + p0.y);
                float2 p1 = unpack2(a1[jj]); h2own[1][jj] = tanh_fast(p1.x + p1.y);
            }
        }
    }

    // ===== FC epilogue: out[b] = h2 . fc_w + fc_b =====
    float s0 = 0.f, s1 = 0.f;
#pragma unroll
    for (int jj = 0; jj < 5; jj++) {
        float w = __ldg(&fc_w[j0 + jj]);
        s0 += h2own[0][jj] * w;
        s1 += h2own[1][jj] * w;
    }
    s0 += __shfl_xor_sync(0xffffffffu, s0, 1);
    s0 += __shfl_xor_sync(0xffffffffu, s0, 2);
    s1 += __shfl_xor_sync(0xffffffffu, s1, 1);
    s1 += __shfl_xor_sync(0xffffffffu, s1, 2);
    if (sub == 0) {
        float fb = __ldg(&fc_b[0]);
        out[b0] = s0 + fb;
        out[b1] = s1 + fb;
    }
}

extern "C" void kernel_launch(void* const* d_in, const int* in_sizes, int n_in,
                              void* d_out, int out_size) {
    (void)in_sizes; (void)n_in; (void)out_size;
    rnn3_kernel<<<NBLOCKS, NTHREADS>>>(
        (const float*)d_in[0],
        (const float*)d_in[1],  (const float*)d_in[2],
        (const float*)d_in[3],  (const float*)d_in[4],
        (const float*)d_in[5],  (const float*)d_in[6],
        (const float*)d_in[7],  (const float*)d_in[8],
        (const float*)d_in[9],  (const float*)d_in[10],
        (const float*)d_in[11], (const float*)d_in[12],
        (const float*)d_in[13], (const float*)d_in[14],
        (float*)d_out);
}

// round 6
// speedup vs baseline: 2.4292x; 1.0015x over previous
#include <cuda_runtime.h>
#include <cstdint>

#define TSTEPS 512
#define H 20
#define BPB 32          // batches/block: 2 warps x 8 groups x 2 batches
#define NTHREADS 64
#define NBLOCKS 256
#define SUBSTRIDE 2008  // floats per sub-copy (2000 + 8 pad -> distinct 16B phases)

typedef unsigned long long u64;

__device__ __forceinline__ void ffma2(u64& acc, u64 a, u64 b) {
    asm("fma.rn.f32x2 %0, %1, %2, %0;" : "+l"(acc) : "l"(a), "l"(b));
}
__device__ __forceinline__ u64 pack2(float lo, float hi) {
    u64 r; asm("mov.b64 %0, {%1, %2};" : "=l"(r) : "f"(lo), "f"(hi)); return r;
}
__device__ __forceinline__ float2 unpack2(u64 v) {
    float2 r; asm("mov.b64 {%0, %1}, %2;" : "=f"(r.x), "=f"(r.y) : "l"(v)); return r;
}
// tanh via ex2.approx + rcp.approx, abs err ~2e-7
__device__ __forceinline__ float tanh_fast(float x) {
    float ax = fminf(fabsf(x), 15.0f);
    float e;
    asm("ex2.approx.f32 %0, %1;" : "=f"(e) : "f"(ax * 2.8853900817779268f));
    float rr;
    asm("rcp.approx.f32 %0, %1;" : "=f"(rr) : "f"(e + 1.0f));
    return copysignf((e - 1.0f) * rr, x);
}

// Butterfly gather within a 4-lane group: input = own 5 h values, output =
// all 20 h values k-pair-packed as u64[10], in per-lane block order
// [sub, sub^1, sub^2, sub^3] (weights in smem are pre-permuted to match).
__device__ __forceinline__ void gather20(const float v[5], u64 hp[10]) {
    float a[10];
#pragma unroll
    for (int i = 0; i < 5; i++) {
        a[i]     = v[i];
        a[5 + i] = __shfl_xor_sync(0xffffffffu, v[i], 1);
    }
#pragma unroll
    for (int q = 0; q < 5; q++) hp[q] = pack2(a[2 * q], a[2 * q + 1]);
    float b[10];
#pragma unroll
    for (int i = 0; i < 10; i++) b[i] = __shfl_xor_sync(0xffffffffu, a[i], 2);
#pragma unroll
    for (int q = 0; q < 5; q++) hp[5 + q] = pack2(b[2 * q], b[2 * q + 1]);
}

__global__ __launch_bounds__(NTHREADS)
void rnn3_kernel(
    const float* __restrict__ x,
    const float* __restrict__ w_ih0, const float* __restrict__ w_hh0,
    const float* __restrict__ b_ih0, const float* __restrict__ b_hh0,
    const float* __restrict__ w_ih1, const float* __restrict__ w_hh1,
    const float* __restrict__ b_ih1, const float* __restrict__ b_hh1,
    const float* __restrict__ w_ih2, const float* __restrict__ w_hh2,
    const float* __restrict__ b_ih2, const float* __restrict__ b_hh2,
    const float* __restrict__ fc_w, const float* __restrict__ fc_b,
    float* __restrict__ out)
{
    // per-sub permuted weight copies: wp[sub][m][j][k],
    // column k maps to original column 5*(sub ^ (k/5)) + k%5.
    // matrices m: 0=w_hh0 1=w_ih1 2=w_hh1 3=w_ih2 4=w_hh2
    __shared__ __align__(16) float wp[4 * SUBSTRIDE];   // 32128 B

    const int tid = threadIdx.x;

    for (int idx = tid; idx < 4 * 2000; idx += NTHREADS) {
        int s   = idx / 2000;
        int rem = idx % 2000;
        int m   = rem / 400;
        int r   = rem % 400;
        int j   = r / H;
        int k   = r % H;
        int oc  = 5 * (s ^ (k / 5)) + (k % 5);
        const float* src = (m == 0) ? w_hh0 : (m == 1) ? w_ih1 :
                           (m == 2) ? w_hh1 : (m == 3) ? w_ih2 : w_hh2;
        wp[s * SUBSTRIDE + (m * H + j) * H + k] = src[j * H + oc];
    }
    __syncthreads();

    const int lane = tid & 31;
    const int warp = tid >> 5;
    const int gi   = lane >> 2;
    const int sub  = lane & 3;
    const int bib0 = warp * 8 + gi;
    const int bib1 = 16 + warp * 8 + gi;
    const int b0   = blockIdx.x * BPB + bib0;
    const int b1   = blockIdx.x * BPB + bib1;
    const int j0   = sub * 5;

    // sub's permuted weight base; matrix m row jj quads at wmS + m*400 + jj*20
    const float* wsub = wp + sub * SUBSTRIDE + j0 * H;

    float bias0[5], bias1[5], bias2[5], wih0r[5];
#pragma unroll
    for (int jj = 0; jj < 5; jj++) {
        int j = j0 + jj;
        bias0[jj] = b_ih0[j] + b_hh0[j];
        bias1[jj] = b_ih1[j] + b_hh1[j];
        bias2[jj] = b_ih2[j] + b_hh2[j];
        wih0r[jj] = w_ih0[j];
    }

    const float* xrow0 = x + (size_t)b0 * TSTEPS;
    const float* xrow1 = x + (size_t)b1 * TSTEPS;

    // persistent state (registers only)
    u64 hp0[2][10], hp1[2][10];     // gathered h0, h1 (k-pair packed)
    float h2own[2][5];              // own 5 rows of h2
#pragma unroll
    for (int q = 0; q < 10; q++) { hp0[0][q] = 0; hp0[1][q] = 0; hp1[0][q] = 0; hp1[1][q] = 0; }
#pragma unroll
    for (int jj = 0; jj < 5; jj++) { h2own[0][jj] = 0.f; h2own[1][jj] = 0.f; }

    float4 xq0 = make_float4(0.f,0.f,0.f,0.f), xq1 = xq0;

#pragma unroll 1
    for (int t = 0; t < TSTEPS; t++) {
        if ((t & 3) == 0) {
            xq0 = __ldg((const float4*)(xrow0 + t));
            xq1 = __ldg((const float4*)(xrow1 + t));
        }
        const int ph = t & 3;
        const float xv0 = (ph == 0) ? xq0.x : (ph == 1) ? xq0.y : (ph == 2) ? xq0.z : xq0.w;
        const float xv1 = (ph == 0) ? xq1.x : (ph == 1) ? xq1.y : (ph == 2) ? xq1.z : xq1.w;

        // ===== Layer 0: h0' = tanh(x*wih0 + bias0 + whh0 @ h0) =====
        float h0n0[5], h0n1[5];
        {
            u64 a0[5], a1[5];
#pragma unroll
            for (int jj = 0; jj < 5; jj++) {
                a0[jj] = pack2(fmaf(xv0, wih0r[jj], bias0[jj]), 0.f);
                a1[jj] = pack2(fmaf(xv1, wih0r[jj], bias0[jj]), 0.f);
            }
            const float* wm = wsub;  // m = 0
#pragma unroll
            for (int q = 0; q < 5; q++) {
#pragma unroll
                for (int jj = 0; jj < 5; jj++) {
                    ulonglong2 wv = ((const ulonglong2*)(wm + jj * H))[q];
                    ffma2(a0[jj], hp0[0][2*q],   wv.x);
                    ffma2(a0[jj], hp0[0][2*q+1], wv.y);
                    ffma2(a1[jj], hp0[1][2*q],   wv.x);
                    ffma2(a1[jj], hp0[1][2*q+1], wv.y);
                }
            }
#pragma unroll
            for (int jj = 0; jj < 5; jj++) {
                float2 p0 = unpack2(a0[jj]); h0n0[jj] = tanh_fast(p0.x + p0.y);
                float2 p1 = unpack2(a1[jj]); h0n1[jj] = tanh_fast(p1.x + p1.y);
            }
        }
        gather20(h0n0, hp0[0]);
        gather20(h0n1, hp0[1]);

        // ===== Layer 1: h1' = tanh(wih1 @ h0' + bias1 + whh1 @ h1) =====
        float h1n0[5], h1n1[5];
        {
            u64 a0[5], a1[5];
#pragma unroll
            for (int jj = 0; jj < 5; jj++) { a0[jj] = pack2(bias1[jj], 0.f); a1[jj] = pack2(bias1[jj], 0.f); }
            const float* wi = wsub + 400;   // m = 1
            const float* wh = wsub + 800;   // m = 2
#pragma unroll
            for (int q = 0; q < 5; q++) {
#pragma unroll
                for (int jj = 0; jj < 5; jj++) {
                    ulonglong2 wiv = ((const ulonglong2*)(wi + jj * H))[q];
                    ulonglong2 whv = ((const ulonglong2*)(wh + jj * H))[q];
                    ffma2(a0[jj], hp0[0][2*q],   wiv.x);
                    ffma2(a0[jj], hp0[0][2*q+1], wiv.y);
                    ffma2(a0[jj], hp1[0][2*q],   whv.x);
                    ffma2(a0[jj], hp1[0][2*q+1], whv.y);
                    ffma2(a1[jj], hp0[1][2*q],   wiv.x);
                    ffma2(a1[jj], hp0[1][2*q+1], wiv.y);
                    ffma2(a1[jj], hp1[1][2*q],   whv.x);
                    ffma2(a1[jj], hp1[1][2*q+1], whv.y);
                }
            }
#pragma unroll
            for (int jj = 0; jj < 5; jj++) {
                float2 p0 = unpack2(a0[jj]); h1n0[jj] = tanh_fast(p0.x + p0.y);
                float2 p1 = unpack2(a1[jj]); h1n1[jj] = tanh_fast(p1.x + p1.y);
            }
        }
        gather20(h1n0, hp1[0]);
        gather20(h1n1, hp1[1]);

        // ===== Layer 2: h2' = tanh(wih2 @ h1' + bias2 + whh2 @ h2) =====
        {
            u64 hp2a[10], hp2b[10];
            gather20(h2own[0], hp2a);
            gather20(h2own[1], hp2b);
            u64 a0[5], a1[5];
#pragma unroll
            for (int jj = 0; jj < 5; jj++) { a0[jj] = pack2(bias2[jj], 0.f); a1[jj] = pack2(bias2[jj], 0.f); }
            const float* wi = wsub + 1200;  // m = 3
            const float* wh = wsub + 1600;  // m = 4
#pragma unroll
            for (int q = 0; q < 5; q++) {
#pragma unroll
                for (int jj = 0; jj < 5; jj++) {
                    ulonglong2 wiv = ((const ulonglong2*)(wi + jj * H))[q];
                    ulonglong2 whv = ((const ulonglong2*)(wh + jj * H))[q];
                    ffma2(a0[jj], hp1[0][2*q],   wiv.x);
                    ffma2(a0[jj], hp1[0][2*q+1], wiv.y);
                    ffma2(a0[jj], hp2a[2*q],     whv.x);
                    ffma2(a0[jj], hp2a[2*q+1],   whv.y);
                    ffma2(a1[jj], hp1[1][2*q],   wiv.x);
                    ffma2(a1[jj], hp1[1][2*q+1], wiv.y);
                    ffma2(a1[jj], hp2b[2*q],     whv.x);
                    ffma2(a1[jj], hp2b[2*q+1],   whv.y);
                }
            }
#pragma unroll
            for (int jj = 0; jj < 5; jj++) {
                float2 p0 = unpack2(a0[jj]); h2own[0][jj] = tanh_fast(p0.x + p0.y);
                float2 p1 = unpack2(a1[jj]); h2own[1][jj] = tanh_fast(p1.x + p1.y);
            }
        }
    }

    // ===== FC epilogue: out[b] = h2 . fc_w + fc_b =====
    float s0 = 0.f, s1 = 0.f;
#pragma unroll
    for (int jj = 0; jj < 5; jj++) {
        float w = __ldg(&fc_w[j0 + jj]);
        s0 += h2own[0][jj] * w;
        s1 += h2own[1][jj] * w;
    }
    s0 += __shfl_xor_sync(0xffffffffu, s0, 1);
    s0 += __shfl_xor_sync(0xffffffffu, s0, 2);
    s1 += __shfl_xor_sync(0xffffffffu, s1, 1);
    s1 += __shfl_xor_sync(0xffffffffu, s1, 2);
    if (sub == 0) {
        float fb = __ldg(&fc_b[0]);
        out[b0] = s0 + fb;
        out[b1] = s1 + fb;
    }
}

extern "C" void kernel_launch(void* const* d_in, const int* in_sizes, int n_in,
                              void* d_out, int out_size) {
    (void)in_sizes; (void)n_in; (void)out_size;
    rnn3_kernel<<<NBLOCKS, NTHREADS>>>(
        (const float*)d_in[0],
        (const float*)d_in[1],  (const float*)d_in[2],
        (const float*)d_in[3],  (const float*)d_in[4],
        (const float*)d_in[5],  (const float*)d_in[6],
        (const float*)d_in[7],  (const float*)d_in[8],
        (const float*)d_in[9],  (const float*)d_in[10],
        (const float*)d_in[11], (const float*)d_in[12],
        (const float*)d_in[13], (const float*)d_in[14],
        (float*)d_out);
}